// round 13
// baseline (speedup 1.0000x reference)
#include <cuda_runtime.h>
#include <cuda_fp16.h>
#include <math_constants.h>
#include <stdint.h>

#define NN 25000
#define EE 250000
#define HH 4
#define DD 64
#define HD 256   // H*D

// ---------------- scratch (device globals; no allocation allowed) -------------
__device__ __align__(16) __half g_act16[NN * HD];  // layer input (fp16)
__device__ __align__(16) __half g_feat16[NN * HD]; // x @ W (fp16)
__device__ __align__(16) __half g_hh[NN * HD];     // final output (score input)
__device__ __align__(16) __half g_w16[3 * HD * HD];
__device__ float g_elp[2 * NN * HH];
__device__ float g_erp[2 * NN * HH];
// pos CSR (by dst)
__device__ int g_cnt[NN];
__device__ int g_off[NN + 1];
__device__ int g_cur[NN];
__device__ int g_csr_src[EE];
__device__ int g_csr_eid[EE];
// neg CSR (by ndst) — used only by score
__device__ int g_ncnt[NN];
__device__ int g_noff[NN + 1];
__device__ int g_ncur[NN];
__device__ int2 g_ncsr[EE];    // (nsrc, eid)

// ---------------- helpers ----------------------------------------------------
__device__ __forceinline__ void mma_f16(float* d, const uint32_t* a, const uint32_t* b) {
    asm volatile(
        "mma.sync.aligned.m16n8k16.row.col.f32.f16.f16.f32 "
        "{%0,%1,%2,%3}, {%4,%5,%6,%7}, {%8,%9}, {%0,%1,%2,%3};"
        : "+f"(d[0]), "+f"(d[1]), "+f"(d[2]), "+f"(d[3])
        : "r"(a[0]), "r"(a[1]), "r"(a[2]), "r"(a[3]), "r"(b[0]), "r"(b[1]));
}

__device__ __forceinline__ uint32_t cvta_smem(const void* p) {
    return (uint32_t)__cvta_generic_to_shared(p);
}

#define CP_ASYNC16(dst, src, sz) \
    asm volatile("cp.async.cg.shared.global [%0], [%1], 16, %2;" :: "r"(dst), "l"(src), "r"(sz))
#define CP_COMMIT() asm volatile("cp.async.commit_group;")
template <int N>
__device__ __forceinline__ void cp_wait() {
    asm volatile("cp.async.wait_group %0;" :: "n"(N));
}

// ---------------- one-time fp32 -> fp16 converts (x and all W, one kernel) ----
#define NX4 (NN * HD / 4)
#define NW4 (3 * HD * HD / 4)
__global__ __launch_bounds__(256) void cvt_all_kernel(const float* __restrict__ x,
                                                      const float* __restrict__ W1,
                                                      const float* __restrict__ W2,
                                                      const float* __restrict__ W3) {
    int t = blockIdx.x * 256 + threadIdx.x;
    float4 v;
    uint2* dst;
    if (t < NX4) {
        v = ((const float4*)x)[t];
        dst = ((uint2*)g_act16) + t;
    } else {
        int u = t - NX4;
        if (u >= NW4) return;
        const float* src = (u < 16384) ? W1 : ((u < 32768) ? W2 : W3);
        v = ((const float4*)src)[u & 16383];
        dst = ((uint2*)g_w16) + u;
    }
    __half2 h0 = __floats2half2_rn(v.x, v.y);
    __half2 h1 = __floats2half2_rn(v.z, v.w);
    uint2 p; p.x = *(uint32_t*)&h0; p.y = *(uint32_t*)&h1;
    *dst = p;
}

// ---------------- CSR build ---------------------------------------------------
__global__ __launch_bounds__(256) void csr_hist_kernel(const int* __restrict__ dst,
                                                       int* __restrict__ cnt) {
    int i = blockIdx.x * blockDim.x + threadIdx.x;
    if (i < EE) atomicAdd(&cnt[dst[i]], 1);
}

__global__ __launch_bounds__(1024) void csr_scan_kernel(const int* __restrict__ cnt,
                                                        int* __restrict__ off,
                                                        int* __restrict__ cur) {
    extern __shared__ int sm[];   // NN ints
    __shared__ int wsum[32];
    const int tid = threadIdx.x;
    const int lane = tid & 31, w = tid >> 5;

    for (int i = tid; i < NN; i += 1024) sm[i] = cnt[i];
    __syncthreads();

    const int base = tid * 25;
    int s = 0;
#pragma unroll
    for (int j = 0; j < 25; j++) {
        int idx = base + j;
        if (idx < NN) s += sm[idx];
    }
    int incl = s;
#pragma unroll
    for (int o = 1; o < 32; o <<= 1) {
        int v = __shfl_up_sync(0xffffffffu, incl, o);
        if (lane >= o) incl += v;
    }
    if (lane == 31) wsum[w] = incl;
    __syncthreads();
    if (w == 0) {
        int t = wsum[lane];
        int ti = t;
#pragma unroll
        for (int o = 1; o < 32; o <<= 1) {
            int v = __shfl_up_sync(0xffffffffu, ti, o);
            if (lane >= o) ti += v;
        }
        wsum[lane] = ti - t;
    }
    __syncthreads();
    int run = wsum[w] + (incl - s);

#pragma unroll
    for (int j = 0; j < 25; j++) {
        int idx = base + j;
        if (idx < NN) {
            int c = sm[idx];
            sm[idx] = run;
            run += c;
        }
    }
    __syncthreads();

    for (int i = tid; i < NN; i += 1024) {
        int o = sm[i];
        off[i] = o;
        cur[i] = o;
    }
    if (tid == 0) off[NN] = EE;
}

__global__ __launch_bounds__(256) void csr_scatter_pos(const int* __restrict__ src,
                                                       const int* __restrict__ dst) {
    int e = blockIdx.x * blockDim.x + threadIdx.x;
    if (e >= EE) return;
    int slot = atomicAdd(&g_cur[dst[e]], 1);
    g_csr_src[slot] = src[e];
    g_csr_eid[slot] = e;
}

__global__ __launch_bounds__(256) void csr_scatter_neg(const int* __restrict__ nsrc,
                                                       const int* __restrict__ ndst) {
    int e = blockIdx.x * blockDim.x + threadIdx.x;
    if (e >= EE) return;
    int slot = atomicAdd(&g_ncur[ndst[e]], 1);
    g_ncsr[slot] = make_int2(nsrc[e], e);
}

// ---------------- FP16 GEMM: 3-stage cp.async + ldmatrix + fused el/er --------
// Tile M=192, N=128, BK=32. grid (131, 2) = 262 CTAs -> single wave at 2/SM.
// 8 warps 2m x 4n: warp tile 96x32 (6x4 m16n8k16 atoms).
// 3-stage dynamic smem pipeline, cp.async wait_group 1 -> each tile's load is
// covered by TWO tiles of compute.
#define BK 32
#define MT 192
#define A_ROWB 80
#define B_ROWB 272
#define A_STAGEB (MT * A_ROWB)              // 15360
#define B_STAGEB (BK * B_ROWB)              // 8704
#define STAGEB   (A_STAGEB + B_STAGEB)      // 24064
#define GEMM_SMEM (3 * STAGEB)              // 72192

__global__ __launch_bounds__(256, 2) void gemm_fused(const __half* __restrict__ Ain,
                                                     const __half* __restrict__ Win,
                                                     const float* __restrict__ alp,
                                                     const float* __restrict__ arp,
                                                     __half* __restrict__ C16) {
    extern __shared__ __align__(16) char smem[];

    const int tid = threadIdx.x;
    const int bm = blockIdx.x * MT;
    const int bn = blockIdx.y * 128;
    const int lane = tid & 31;
    const int wid = tid >> 5;
    const int wm = (wid >> 2) * 96;   // 0 / 96
    const int wn = (wid & 3) * 32;
    const int g  = lane >> 2;
    const int c  = lane & 3;
    const int c2 = c * 2;

    const uint32_t smem_u32 = cvta_smem(smem);

    // --- A producer: 3 rows per thread (r, r+64, r+128), one 16B chunk each ---
    const int arow = tid >> 2;
    const int acol = (tid & 3) * 8;
    const uint32_t asz0 = (bm + arow)       < NN ? 16u : 0u;
    const uint32_t asz1 = (bm + arow + 64)  < NN ? 16u : 0u;
    const uint32_t asz2 = (bm + arow + 128) < NN ? 16u : 0u;
    const __half* asrc0 = Ain + (size_t)(bm + arow) * 256 + acol;
    const __half* asrc1 = asrc0 + (size_t)64 * 256;
    const __half* asrc2 = asrc0 + (size_t)128 * 256;
    const uint32_t adst0 = smem_u32 + arow * A_ROWB + (tid & 3) * 16;
    const uint32_t adst1 = adst0 + 64 * A_ROWB;
    const uint32_t adst2 = adst0 + 128 * A_ROWB;
    // --- B producer ---
    const int bkrow = tid >> 3, bch = (tid & 7) * 2;
    const __half* bsrc0 = Win + (size_t)bkrow * 256 + bn + bch * 8;
    const uint32_t bdst0 = smem_u32 + A_STAGEB + bkrow * B_ROWB + bch * 16;

    // --- ldmatrix consumer bases ---
    const uint32_t a_lm0 = smem_u32 + (wm + (lane & 15)) * A_ROWB + (lane >> 4) * 16;
    const uint32_t b_lm0 = smem_u32 + A_STAGEB + (lane & 15) * B_ROWB
                         + ((wn >> 3) + (lane >> 4)) * 16;

    float acc[6][4][4];
#pragma unroll
    for (int i = 0; i < 6; i++)
#pragma unroll
        for (int j = 0; j < 4; j++)
#pragma unroll
            for (int t = 0; t < 4; t++) acc[i][j][t] = 0.f;

    // issue tiles 0 and 1 as separate groups
#pragma unroll
    for (int pre = 0; pre < 2; pre++) {
        const int ko = pre * BK;
        const uint32_t so = pre * STAGEB;
        CP_ASYNC16(adst0 + so, asrc0 + ko, asz0);
        CP_ASYNC16(adst1 + so, asrc1 + ko, asz1);
        CP_ASYNC16(adst2 + so, asrc2 + ko, asz2);
        const __half* bs = bsrc0 + (size_t)ko * 256;
        CP_ASYNC16(bdst0 + so, bs, 16);
        CP_ASYNC16(bdst0 + so + 16, bs + 8, 16);
        CP_COMMIT();
    }

    int stage = 0;
    for (int kt = 0; kt < 8; kt++) {
        if (kt == 7) cp_wait<0>(); else cp_wait<1>();
        __syncthreads();
        if (kt < 6) {
            const int ko = (kt + 2) * BK;
            // stage being written = (kt+2)%3; all warps finished computing it
            // in iteration kt-1 (guaranteed by the sync above).
            const uint32_t so = ((stage + 2 >= 3) ? stage - 1 : stage + 2) * STAGEB;
            CP_ASYNC16(adst0 + so, asrc0 + ko, asz0);
            CP_ASYNC16(adst1 + so, asrc1 + ko, asz1);
            CP_ASYNC16(adst2 + so, asrc2 + ko, asz2);
            const __half* bs = bsrc0 + (size_t)ko * 256;
            CP_ASYNC16(bdst0 + so, bs, 16);
            CP_ASYNC16(bdst0 + so + 16, bs + 8, 16);
            CP_COMMIT();
        }
        const uint32_t aS = a_lm0 + stage * STAGEB;
        const uint32_t bS = b_lm0 + stage * STAGEB;
#pragma unroll
        for (int ks = 0; ks < 2; ks++) {
            uint32_t bfr[4][2];
#pragma unroll
            for (int jp = 0; jp < 2; jp++) {
                const uint32_t addr = bS + ks * (16 * B_ROWB) + jp * 32;
                asm volatile(
                    "ldmatrix.sync.aligned.m8n8.x4.trans.shared.b16 {%0,%1,%2,%3}, [%4];"
                    : "=r"(bfr[2*jp][0]), "=r"(bfr[2*jp][1]),
                      "=r"(bfr[2*jp+1][0]), "=r"(bfr[2*jp+1][1])
                    : "r"(addr));
            }
#pragma unroll
            for (int i = 0; i < 6; i++) {
                uint32_t afr[4];
                const uint32_t addr = aS + i * (16 * A_ROWB) + ks * 32;
                asm volatile(
                    "ldmatrix.sync.aligned.m8n8.x4.shared.b16 {%0,%1,%2,%3}, [%4];"
                    : "=r"(afr[0]), "=r"(afr[1]), "=r"(afr[2]), "=r"(afr[3])
                    : "r"(addr));
#pragma unroll
                for (int j = 0; j < 4; j++) mma_f16(acc[i][j], afr, bfr[j]);
            }
        }
        stage = (stage + 1 >= 3) ? 0 : stage + 1;
    }

    // ---- epilogue: fp16 feat store + fused el/er partials ----
    const int colbase = bn + wn;
    const int hh_ = colbase >> 6;
    const int q_  = (colbase >> 5) & 1;
    float alv[4][2], arv[4][2];
#pragma unroll
    for (int j = 0; j < 4; j++) {
        int col = colbase + j * 8 + c2;
        alv[j][0] = alp[col];     alv[j][1] = alp[col + 1];
        arv[j][0] = arp[col];     arv[j][1] = arp[col + 1];
    }

#pragma unroll
    for (int i = 0; i < 6; i++) {
        const int r = bm + wm + i * 16 + g;
        float pel0 = 0.f, per0 = 0.f, pel1 = 0.f, per1 = 0.f;
#pragma unroll
        for (int j = 0; j < 4; j++) {
            const int col = colbase + j * 8 + c2;
            pel0 += acc[i][j][0] * alv[j][0] + acc[i][j][1] * alv[j][1];
            per0 += acc[i][j][0] * arv[j][0] + acc[i][j][1] * arv[j][1];
            pel1 += acc[i][j][2] * alv[j][0] + acc[i][j][3] * alv[j][1];
            per1 += acc[i][j][2] * arv[j][0] + acc[i][j][3] * arv[j][1];
            __half2 h01 = __floats2half2_rn(acc[i][j][0], acc[i][j][1]);
            __half2 h23 = __floats2half2_rn(acc[i][j][2], acc[i][j][3]);
            if (r < NN)     *(__half2*)(C16 + r * 256 + col)       = h01;
            if (r + 8 < NN) *(__half2*)(C16 + (r + 8) * 256 + col) = h23;
        }
#pragma unroll
        for (int o = 1; o <= 2; o <<= 1) {
            pel0 += __shfl_xor_sync(0xffffffffu, pel0, o);
            per0 += __shfl_xor_sync(0xffffffffu, per0, o);
            pel1 += __shfl_xor_sync(0xffffffffu, pel1, o);
            per1 += __shfl_xor_sync(0xffffffffu, per1, o);
        }
        if (c == 0) {
            if (r < NN) {
                g_elp[q_ * (NN * HH) + r * HH + hh_] = pel0;
                g_erp[q_ * (NN * HH) + r * HH + hh_] = per0;
            }
            if (r + 8 < NN) {
                g_elp[q_ * (NN * HH) + (r + 8) * HH + hh_] = pel1;
                g_erp[q_ * (NN * HH) + (r + 8) * HH + hh_] = per1;
            }
        }
    }
}

// ---------------- fused edge softmax + aggregation + bias/relu ----------------
__global__ __launch_bounds__(256) void fused_edge_kernel(const float* __restrict__ b,
                                                         __half* __restrict__ out) {
    const int n = (blockIdx.x * blockDim.x + threadIdx.x) >> 5;
    const int lane = threadIdx.x & 31;
    if (n >= NN) return;

    const int off = g_off[n];
    const int deg = g_off[n + 1] - off;
    const int h = lane >> 3;

    const float erh = g_erp[n * HH + h] + g_erp[NN * HH + n * HH + h];

    float acc[8];
#pragma unroll
    for (int j = 0; j < 8; j++) acc[j] = 0.f;
    float ssum = 0.f;

    for (int base = 0; base < deg; base += 32) {
        const int myi = base + lane;
        const int sv = (myi < deg) ? g_csr_src[off + myi] : 0;
        const int cnt = min(32, deg - base);
#pragma unroll 4
        for (int j = 0; j < cnt; j++) {
            const int s = __shfl_sync(0xffffffffu, sv, j);
            float e = g_elp[s * HH + h] + g_elp[NN * HH + s * HH + h] + erh;
            e = e > 0.f ? e : 0.2f * e;
            const float a = __expf(e);
            ssum += a;
            const uint4 p = *(const uint4*)(g_feat16 + s * HD + lane * 8);
            const __half2* ph = (const __half2*)&p;
            float2 f0 = __half22float2(ph[0]);
            float2 f1 = __half22float2(ph[1]);
            float2 f2 = __half22float2(ph[2]);
            float2 f3 = __half22float2(ph[3]);
            acc[0] += a * f0.x; acc[1] += a * f0.y;
            acc[2] += a * f1.x; acc[3] += a * f1.y;
            acc[4] += a * f2.x; acc[5] += a * f2.y;
            acc[6] += a * f3.x; acc[7] += a * f3.y;
        }
    }
    const float inv = (ssum > 0.f) ? (1.f / ssum) : 0.f;

    const float4 b0 = *(const float4*)(b + lane * 8);
    const float4 b1 = *(const float4*)(b + lane * 8 + 4);
    float o0 = fmaxf(acc[0] * inv + b0.x, 0.f);
    float o1 = fmaxf(acc[1] * inv + b0.y, 0.f);
    float o2 = fmaxf(acc[2] * inv + b0.z, 0.f);
    float o3 = fmaxf(acc[3] * inv + b0.w, 0.f);
    float o4 = fmaxf(acc[4] * inv + b1.x, 0.f);
    float o5 = fmaxf(acc[5] * inv + b1.y, 0.f);
    float o6 = fmaxf(acc[6] * inv + b1.z, 0.f);
    float o7 = fmaxf(acc[7] * inv + b1.w, 0.f);

    __half2 p0 = __floats2half2_rn(o0, o1);
    __half2 p1 = __floats2half2_rn(o2, o3);
    __half2 p2 = __floats2half2_rn(o4, o5);
    __half2 p3 = __floats2half2_rn(o6, o7);
    uint4 pk;
    pk.x = *(uint32_t*)&p0; pk.y = *(uint32_t*)&p1;
    pk.z = *(uint32_t*)&p2; pk.w = *(uint32_t*)&p3;
    ((uint4*)(out + n * HD))[lane] = pk;
}

// ---------------- CSR-structured dot scores ------------------------------------
__global__ __launch_bounds__(256) void score_kernel(float* __restrict__ out) {
    const int w = (blockIdx.x * blockDim.x + threadIdx.x) >> 5;
    const int lane = threadIdx.x & 31;
    if (w >= 2 * NN) return;
    const bool pos = w < NN;
    const int n = pos ? w : w - NN;

    const int* offp = pos ? g_off : g_noff;
    const int off = offp[n];
    const int deg = offp[n + 1] - off;
    if (deg == 0) return;

    const uint4 vp = ((const uint4*)(g_hh + n * HD))[lane];
    const __half2* vh = (const __half2*)&vp;
    const float2 v0 = __half22float2(vh[0]), v1 = __half22float2(vh[1]);
    const float2 v2 = __half22float2(vh[2]), v3 = __half22float2(vh[3]);

    float* obase = out + (pos ? 0 : EE * HH);

    for (int base = 0; base < deg; base += 32) {
        const int myi = base + lane;
        int sv = 0, ev = 0;
        if (myi < deg) {
            if (pos) { sv = g_csr_src[off + myi]; ev = g_csr_eid[off + myi]; }
            else     { int2 t = g_ncsr[off + myi]; sv = t.x; ev = t.y; }
        }
        const int cnt = min(32, deg - base);
        for (int j = 0; j < cnt; j++) {
            const int s  = __shfl_sync(0xffffffffu, sv, j);
            const int ei = __shfl_sync(0xffffffffu, ev, j);
            const uint4 up = *(const uint4*)(g_hh + s * HD + lane * 8);
            const __half2* uh = (const __half2*)&up;
            const float2 u0 = __half22float2(uh[0]), u1 = __half22float2(uh[1]);
            const float2 u2 = __half22float2(uh[2]), u3 = __half22float2(uh[3]);
            float d = u0.x * v0.x + u0.y * v0.y + u1.x * v1.x + u1.y * v1.y +
                      u2.x * v2.x + u2.y * v2.y + u3.x * v3.x + u3.y * v3.y;
#pragma unroll
            for (int o = 4; o >= 1; o >>= 1) d += __shfl_down_sync(0xffffffffu, d, o, 8);
            if ((lane & 7) == 0) obase[ei * HH + (lane >> 3)] = d;
        }
    }
}

// ---------------- launch -------------------------------------------------------
extern "C" void kernel_launch(void* const* d_in, const int* in_sizes, int n_in,
                              void* d_out, int out_size) {
    const float* x    = (const float*)d_in[0];
    const int* src    = (const int*)d_in[1];
    const int* dst    = (const int*)d_in[2];
    const int* nsrc   = (const int*)d_in[3];
    const int* ndst   = (const int*)d_in[4];
    const float* W[3]  = {(const float*)d_in[5], (const float*)d_in[9],  (const float*)d_in[13]};
    const float* al[3] = {(const float*)d_in[6], (const float*)d_in[10], (const float*)d_in[14]};
    const float* ar[3] = {(const float*)d_in[7], (const float*)d_in[11], (const float*)d_in[15]};
    const float* bb[3] = {(const float*)d_in[8], (const float*)d_in[12], (const float*)d_in[16]};
    float* out = (float*)d_out;

    __half* actbuf = nullptr;
    cudaGetSymbolAddress((void**)&actbuf, g_act16);
    __half* featbuf = nullptr;
    cudaGetSymbolAddress((void**)&featbuf, g_feat16);
    __half* hhbuf = nullptr;
    cudaGetSymbolAddress((void**)&hhbuf, g_hh);
    __half* wbuf = nullptr;
    cudaGetSymbolAddress((void**)&wbuf, g_w16);
    int* cntbuf = nullptr;
    cudaGetSymbolAddress((void**)&cntbuf, g_cnt);
    int* ncntbuf = nullptr;
    cudaGetSymbolAddress((void**)&ncntbuf, g_ncnt);
    int* offbuf = nullptr;
    cudaGetSymbolAddress((void**)&offbuf, g_off);
    int* curbuf = nullptr;
    cudaGetSymbolAddress((void**)&curbuf, g_cur);
    int* noffbuf = nullptr;
    cudaGetSymbolAddress((void**)&noffbuf, g_noff);
    int* ncurbuf = nullptr;
    cudaGetSymbolAddress((void**)&ncurbuf, g_ncur);

    static cudaStream_t s_side = nullptr;
    static cudaEvent_t s_fork = nullptr, s_join1 = nullptr, s_join2 = nullptr;
    if (s_side == nullptr) {
        cudaStreamCreateWithFlags(&s_side, cudaStreamNonBlocking);
        cudaEventCreateWithFlags(&s_fork, cudaEventDisableTiming);
        cudaEventCreateWithFlags(&s_join1, cudaEventDisableTiming);
        cudaEventCreateWithFlags(&s_join2, cudaEventDisableTiming);
        const int scan_smem0 = NN * (int)sizeof(int);
        cudaFuncSetAttribute(csr_scan_kernel, cudaFuncAttributeMaxDynamicSharedMemorySize, scan_smem0);
        cudaFuncSetAttribute(gemm_fused, cudaFuncAttributeMaxDynamicSharedMemorySize, GEMM_SMEM);
    }

    const int scan_smem = NN * (int)sizeof(int);

    dim3 gemm_grid((NN + MT - 1) / MT, 2);   // (131, 2) = 262 CTAs: single wave
    const int cvt_blocks   = (NX4 + NW4 + 255) / 256;
    const int node_blocks  = (NN * 32 + 255) / 256;
    const int score_blocks = (2 * NN * 32 + 255) / 256;
    const int e_blocks     = (EE + 255) / 256;

    // ---- fork: CSR builds on side stream ----
    cudaEventRecord(s_fork, 0);
    cudaStreamWaitEvent(s_side, s_fork, 0);
    cudaMemsetAsync(cntbuf, 0, NN * sizeof(int), s_side);
    csr_hist_kernel<<<e_blocks, 256, 0, s_side>>>(dst, cntbuf);
    csr_scan_kernel<<<1, 1024, scan_smem, s_side>>>(cntbuf, offbuf, curbuf);
    csr_scatter_pos<<<e_blocks, 256, 0, s_side>>>(src, dst);
    cudaEventRecord(s_join1, s_side);
    cudaMemsetAsync(ncntbuf, 0, NN * sizeof(int), s_side);
    csr_hist_kernel<<<e_blocks, 256, 0, s_side>>>(ndst, ncntbuf);
    csr_scan_kernel<<<1, 1024, scan_smem, s_side>>>(ncntbuf, noffbuf, ncurbuf);
    csr_scatter_neg<<<e_blocks, 256, 0, s_side>>>(nsrc, ndst);
    cudaEventRecord(s_join2, s_side);

    // ---- main stream: converts + layer-1 GEMM (independent of CSR) ----
    cvt_all_kernel<<<cvt_blocks, 256>>>(x, W[0], W[1], W[2]);
    gemm_fused<<<gemm_grid, 256, GEMM_SMEM>>>(actbuf, wbuf, al[0], ar[0], featbuf);

    cudaStreamWaitEvent(0, s_join1, 0);
    fused_edge_kernel<<<node_blocks, 256>>>(bb[0], actbuf);
    for (int l = 1; l < 3; l++) {
        gemm_fused<<<gemm_grid, 256, GEMM_SMEM>>>(actbuf, wbuf + l * HD * HD, al[l], ar[l], featbuf);
        fused_edge_kernel<<<node_blocks, 256>>>(bb[l], (l == 2) ? hhbuf : actbuf);
    }
    cudaStreamWaitEvent(0, s_join2, 0);
    score_kernel<<<score_blocks, 256>>>(out);
}

// round 14
// speedup vs baseline: 1.0315x; 1.0315x over previous
#include <cuda_runtime.h>
#include <cuda_fp16.h>
#include <math_constants.h>
#include <stdint.h>

#define NN 25000
#define EE 250000
#define HH 4
#define DD 64
#define HD 256   // H*D

// ---------------- scratch (device globals; no allocation allowed) -------------
__device__ __align__(16) __half g_act16[NN * HD];  // layer input (fp16)
__device__ __align__(16) __half g_feat16[NN * HD]; // x @ W (fp16)
__device__ __align__(16) __half g_hh[NN * HD];     // final output (score input)
__device__ __align__(16) __half g_w16[3 * HD * HD];
__device__ float g_elp[2 * NN * HH];
__device__ float g_erp[2 * NN * HH];
// pos CSR (by dst)
__device__ int g_cnt[NN];
__device__ int g_off[NN + 1];
__device__ int g_cur[NN];
__device__ int g_csr_src[EE];
__device__ int g_csr_eid[EE];
// neg CSR (by ndst) — used only by score
__device__ int g_ncnt[NN];
__device__ int g_noff[NN + 1];
__device__ int g_ncur[NN];
__device__ int2 g_ncsr[EE];    // (nsrc, eid)

// ---------------- helpers ----------------------------------------------------
__device__ __forceinline__ void mma_f16(float* d, const uint32_t* a, const uint32_t* b) {
    asm volatile(
        "mma.sync.aligned.m16n8k16.row.col.f32.f16.f16.f32 "
        "{%0,%1,%2,%3}, {%4,%5,%6,%7}, {%8,%9}, {%0,%1,%2,%3};"
        : "+f"(d[0]), "+f"(d[1]), "+f"(d[2]), "+f"(d[3])
        : "r"(a[0]), "r"(a[1]), "r"(a[2]), "r"(a[3]), "r"(b[0]), "r"(b[1]));
}

__device__ __forceinline__ uint32_t cvta_smem(const void* p) {
    return (uint32_t)__cvta_generic_to_shared(p);
}

#define CP_ASYNC16(dst, src, sz) \
    asm volatile("cp.async.cg.shared.global [%0], [%1], 16, %2;" :: "r"(dst), "l"(src), "r"(sz))
#define CP_COMMIT() asm volatile("cp.async.commit_group;")
template <int N>
__device__ __forceinline__ void cp_wait() {
    asm volatile("cp.async.wait_group %0;" :: "n"(N));
}

// ---------------- one-time fp32 -> fp16 converts (x and all W, one kernel) ----
#define NX4 (NN * HD / 4)
#define NW4 (3 * HD * HD / 4)
__global__ __launch_bounds__(256) void cvt_all_kernel(const float* __restrict__ x,
                                                      const float* __restrict__ W1,
                                                      const float* __restrict__ W2,
                                                      const float* __restrict__ W3) {
    int t = blockIdx.x * 256 + threadIdx.x;
    float4 v;
    uint2* dst;
    if (t < NX4) {
        v = ((const float4*)x)[t];
        dst = ((uint2*)g_act16) + t;
    } else {
        int u = t - NX4;
        if (u >= NW4) return;
        const float* src = (u < 16384) ? W1 : ((u < 32768) ? W2 : W3);
        v = ((const float4*)src)[u & 16383];
        dst = ((uint2*)g_w16) + u;
    }
    __half2 h0 = __floats2half2_rn(v.x, v.y);
    __half2 h1 = __floats2half2_rn(v.z, v.w);
    uint2 p; p.x = *(uint32_t*)&h0; p.y = *(uint32_t*)&h1;
    *dst = p;
}

// ---------------- CSR build ---------------------------------------------------
__global__ __launch_bounds__(256) void csr_hist_kernel(const int* __restrict__ dst,
                                                       int* __restrict__ cnt) {
    int i = blockIdx.x * blockDim.x + threadIdx.x;
    if (i < EE) atomicAdd(&cnt[dst[i]], 1);
}

__global__ __launch_bounds__(1024) void csr_scan_kernel(const int* __restrict__ cnt,
                                                        int* __restrict__ off,
                                                        int* __restrict__ cur) {
    extern __shared__ int sm[];   // NN ints
    __shared__ int wsum[32];
    const int tid = threadIdx.x;
    const int lane = tid & 31, w = tid >> 5;

    for (int i = tid; i < NN; i += 1024) sm[i] = cnt[i];
    __syncthreads();

    const int base = tid * 25;
    int s = 0;
#pragma unroll
    for (int j = 0; j < 25; j++) {
        int idx = base + j;
        if (idx < NN) s += sm[idx];
    }
    int incl = s;
#pragma unroll
    for (int o = 1; o < 32; o <<= 1) {
        int v = __shfl_up_sync(0xffffffffu, incl, o);
        if (lane >= o) incl += v;
    }
    if (lane == 31) wsum[w] = incl;
    __syncthreads();
    if (w == 0) {
        int t = wsum[lane];
        int ti = t;
#pragma unroll
        for (int o = 1; o < 32; o <<= 1) {
            int v = __shfl_up_sync(0xffffffffu, ti, o);
            if (lane >= o) ti += v;
        }
        wsum[lane] = ti - t;
    }
    __syncthreads();
    int run = wsum[w] + (incl - s);

#pragma unroll
    for (int j = 0; j < 25; j++) {
        int idx = base + j;
        if (idx < NN) {
            int c = sm[idx];
            sm[idx] = run;
            run += c;
        }
    }
    __syncthreads();

    for (int i = tid; i < NN; i += 1024) {
        int o = sm[i];
        off[i] = o;
        cur[i] = o;
    }
    if (tid == 0) off[NN] = EE;
}

__global__ __launch_bounds__(256) void csr_scatter_pos(const int* __restrict__ src,
                                                       const int* __restrict__ dst) {
    int e = blockIdx.x * blockDim.x + threadIdx.x;
    if (e >= EE) return;
    int slot = atomicAdd(&g_cur[dst[e]], 1);
    g_csr_src[slot] = src[e];
    g_csr_eid[slot] = e;
}

__global__ __launch_bounds__(256) void csr_scatter_neg(const int* __restrict__ nsrc,
                                                       const int* __restrict__ ndst) {
    int e = blockIdx.x * blockDim.x + threadIdx.x;
    if (e >= EE) return;
    int slot = atomicAdd(&g_ncur[ndst[e]], 1);
    g_ncsr[slot] = make_int2(nsrc[e], e);
}

// ---------------- FP16 GEMM (R12 double-buffer version, known-good) -----------
#define BK 32
#define MT 192
#define A_ROWB 80
#define B_ROWB 272
#define A_STAGEB (MT * A_ROWB)    // 15360
#define B_STAGEB (BK * B_ROWB)    // 8704

__global__ __launch_bounds__(256, 2) void gemm_fused(const __half* __restrict__ Ain,
                                                     const __half* __restrict__ Win,
                                                     const float* __restrict__ alp,
                                                     const float* __restrict__ arp,
                                                     __half* __restrict__ C16) {
    __shared__ __align__(16) char smem[2 * (A_STAGEB + B_STAGEB)];

    const int tid = threadIdx.x;
    const int bm = blockIdx.x * MT;
    const int bn = blockIdx.y * 128;
    const int lane = tid & 31;
    const int wid = tid >> 5;
    const int wm = (wid >> 2) * 96;   // 0 / 96
    const int wn = (wid & 3) * 32;
    const int g  = lane >> 2;
    const int c  = lane & 3;
    const int c2 = c * 2;

    const uint32_t smem_u32 = cvta_smem(smem);

    const int arow = tid >> 2;
    const int acol = (tid & 3) * 8;
    const uint32_t asz0 = (bm + arow)       < NN ? 16u : 0u;
    const uint32_t asz1 = (bm + arow + 64)  < NN ? 16u : 0u;
    const uint32_t asz2 = (bm + arow + 128) < NN ? 16u : 0u;
    const __half* asrc0 = Ain + (size_t)(bm + arow) * 256 + acol;
    const __half* asrc1 = asrc0 + (size_t)64 * 256;
    const __half* asrc2 = asrc0 + (size_t)128 * 256;
    const uint32_t adst0 = smem_u32 + arow * A_ROWB + (tid & 3) * 16;
    const uint32_t adst1 = adst0 + 64 * A_ROWB;
    const uint32_t adst2 = adst0 + 128 * A_ROWB;
    const int bkrow = tid >> 3, bch = (tid & 7) * 2;
    const __half* bsrc0 = Win + (size_t)bkrow * 256 + bn + bch * 8;
    const uint32_t bdst0 = smem_u32 + 2 * A_STAGEB + bkrow * B_ROWB + bch * 16;

    const uint32_t a_lm0 = smem_u32 + (wm + (lane & 15)) * A_ROWB + (lane >> 4) * 16;
    const uint32_t b_lm0 = smem_u32 + 2 * A_STAGEB + (lane & 15) * B_ROWB
                         + ((wn >> 3) + (lane >> 4)) * 16;

    float acc[6][4][4];
#pragma unroll
    for (int i = 0; i < 6; i++)
#pragma unroll
        for (int j = 0; j < 4; j++)
#pragma unroll
            for (int t = 0; t < 4; t++) acc[i][j][t] = 0.f;

    CP_ASYNC16(adst0, asrc0, asz0);
    CP_ASYNC16(adst1, asrc1, asz1);
    CP_ASYNC16(adst2, asrc2, asz2);
    CP_ASYNC16(bdst0, bsrc0, 16);
    CP_ASYNC16(bdst0 + 16, bsrc0 + 8, 16);
    CP_COMMIT();

    for (int kt = 0; kt < 8; kt++) {
        cp_wait<0>();
        __syncthreads();
        if (kt < 7) {
            const int nx = kt + 1, s = nx & 1;
            const int ko = nx * BK;
            const uint32_t ao = s * A_STAGEB;
            CP_ASYNC16(adst0 + ao, asrc0 + ko, asz0);
            CP_ASYNC16(adst1 + ao, asrc1 + ko, asz1);
            CP_ASYNC16(adst2 + ao, asrc2 + ko, asz2);
            const __half* bs = bsrc0 + (size_t)ko * 256;
            const uint32_t bd = bdst0 + s * B_STAGEB;
            CP_ASYNC16(bd, bs, 16);
            CP_ASYNC16(bd + 16, bs + 8, 16);
            CP_COMMIT();
        }
        const int s = kt & 1;
        const uint32_t aS = a_lm0 + s * A_STAGEB;
        const uint32_t bS = b_lm0 + s * B_STAGEB;
#pragma unroll
        for (int ks = 0; ks < 2; ks++) {
            uint32_t bfr[4][2];
#pragma unroll
            for (int jp = 0; jp < 2; jp++) {
                const uint32_t addr = bS + ks * (16 * B_ROWB) + jp * 32;
                asm volatile(
                    "ldmatrix.sync.aligned.m8n8.x4.trans.shared.b16 {%0,%1,%2,%3}, [%4];"
                    : "=r"(bfr[2*jp][0]), "=r"(bfr[2*jp][1]),
                      "=r"(bfr[2*jp+1][0]), "=r"(bfr[2*jp+1][1])
                    : "r"(addr));
            }
#pragma unroll
            for (int i = 0; i < 6; i++) {
                uint32_t afr[4];
                const uint32_t addr = aS + i * (16 * A_ROWB) + ks * 32;
                asm volatile(
                    "ldmatrix.sync.aligned.m8n8.x4.shared.b16 {%0,%1,%2,%3}, [%4];"
                    : "=r"(afr[0]), "=r"(afr[1]), "=r"(afr[2]), "=r"(afr[3])
                    : "r"(addr));
#pragma unroll
                for (int j = 0; j < 4; j++) mma_f16(acc[i][j], afr, bfr[j]);
            }
        }
    }

    // ---- epilogue: fp16 feat store + fused el/er partials ----
    const int colbase = bn + wn;
    const int hh_ = colbase >> 6;
    const int q_  = (colbase >> 5) & 1;
    float alv[4][2], arv[4][2];
#pragma unroll
    for (int j = 0; j < 4; j++) {
        int col = colbase + j * 8 + c2;
        alv[j][0] = alp[col];     alv[j][1] = alp[col + 1];
        arv[j][0] = arp[col];     arv[j][1] = arp[col + 1];
    }

#pragma unroll
    for (int i = 0; i < 6; i++) {
        const int r = bm + wm + i * 16 + g;
        float pel0 = 0.f, per0 = 0.f, pel1 = 0.f, per1 = 0.f;
#pragma unroll
        for (int j = 0; j < 4; j++) {
            const int col = colbase + j * 8 + c2;
            pel0 += acc[i][j][0] * alv[j][0] + acc[i][j][1] * alv[j][1];
            per0 += acc[i][j][0] * arv[j][0] + acc[i][j][1] * arv[j][1];
            pel1 += acc[i][j][2] * alv[j][0] + acc[i][j][3] * alv[j][1];
            per1 += acc[i][j][2] * arv[j][0] + acc[i][j][3] * arv[j][1];
            __half2 h01 = __floats2half2_rn(acc[i][j][0], acc[i][j][1]);
            __half2 h23 = __floats2half2_rn(acc[i][j][2], acc[i][j][3]);
            if (r < NN)     *(__half2*)(C16 + r * 256 + col)       = h01;
            if (r + 8 < NN) *(__half2*)(C16 + (r + 8) * 256 + col) = h23;
        }
#pragma unroll
        for (int o = 1; o <= 2; o <<= 1) {
            pel0 += __shfl_xor_sync(0xffffffffu, pel0, o);
            per0 += __shfl_xor_sync(0xffffffffu, per0, o);
            pel1 += __shfl_xor_sync(0xffffffffu, pel1, o);
            per1 += __shfl_xor_sync(0xffffffffu, per1, o);
        }
        if (c == 0) {
            if (r < NN) {
                g_elp[q_ * (NN * HH) + r * HH + hh_] = pel0;
                g_erp[q_ * (NN * HH) + r * HH + hh_] = per0;
            }
            if (r + 8 < NN) {
                g_elp[q_ * (NN * HH) + (r + 8) * HH + hh_] = pel1;
                g_erp[q_ * (NN * HH) + (r + 8) * HH + hh_] = per1;
            }
        }
    }
}

// ---------------- fused edge softmax + aggregation + bias/relu ----------------
// Warp per node; inner loop batches 4 edges: all 12 independent loads issued
// before any consumption (MLP ~12 instead of serial per-edge latency chain).
// Accumulation order identical to the scalar loop -> bit-identical results.
__global__ __launch_bounds__(256) void fused_edge_kernel(const float* __restrict__ b,
                                                         __half* __restrict__ out) {
    const int n = (blockIdx.x * blockDim.x + threadIdx.x) >> 5;
    const int lane = threadIdx.x & 31;
    if (n >= NN) return;

    const int off = g_off[n];
    const int deg = g_off[n + 1] - off;
    const int h = lane >> 3;

    const float erh = g_erp[n * HH + h] + g_erp[NN * HH + n * HH + h];

    float acc[8];
#pragma unroll
    for (int j = 0; j < 8; j++) acc[j] = 0.f;
    float ssum = 0.f;

    for (int base = 0; base < deg; base += 32) {
        const int myi = base + lane;
        const int sv = (myi < deg) ? g_csr_src[off + myi] : 0;
        const int cnt = min(32, deg - base);
        int j = 0;
        for (; j + 4 <= cnt; j += 4) {
            int s[4];
#pragma unroll
            for (int k = 0; k < 4; k++) s[k] = __shfl_sync(0xffffffffu, sv, j + k);
            float el0[4], el1[4];
            uint4 p[4];
#pragma unroll
            for (int k = 0; k < 4; k++) el0[k] = g_elp[s[k] * HH + h];
#pragma unroll
            for (int k = 0; k < 4; k++) el1[k] = g_elp[NN * HH + s[k] * HH + h];
#pragma unroll
            for (int k = 0; k < 4; k++)
                p[k] = *(const uint4*)(g_feat16 + s[k] * HD + lane * 8);
#pragma unroll
            for (int k = 0; k < 4; k++) {
                float e = el0[k] + el1[k] + erh;
                e = e > 0.f ? e : 0.2f * e;
                const float a = __expf(e);
                ssum += a;
                const __half2* ph = (const __half2*)&p[k];
                float2 f0 = __half22float2(ph[0]);
                float2 f1 = __half22float2(ph[1]);
                float2 f2 = __half22float2(ph[2]);
                float2 f3 = __half22float2(ph[3]);
                acc[0] += a * f0.x; acc[1] += a * f0.y;
                acc[2] += a * f1.x; acc[3] += a * f1.y;
                acc[4] += a * f2.x; acc[5] += a * f2.y;
                acc[6] += a * f3.x; acc[7] += a * f3.y;
            }
        }
        for (; j < cnt; j++) {
            const int s = __shfl_sync(0xffffffffu, sv, j);
            float e = g_elp[s * HH + h] + g_elp[NN * HH + s * HH + h] + erh;
            e = e > 0.f ? e : 0.2f * e;
            const float a = __expf(e);
            ssum += a;
            const uint4 p = *(const uint4*)(g_feat16 + s * HD + lane * 8);
            const __half2* ph = (const __half2*)&p;
            float2 f0 = __half22float2(ph[0]);
            float2 f1 = __half22float2(ph[1]);
            float2 f2 = __half22float2(ph[2]);
            float2 f3 = __half22float2(ph[3]);
            acc[0] += a * f0.x; acc[1] += a * f0.y;
            acc[2] += a * f1.x; acc[3] += a * f1.y;
            acc[4] += a * f2.x; acc[5] += a * f2.y;
            acc[6] += a * f3.x; acc[7] += a * f3.y;
        }
    }
    const float inv = (ssum > 0.f) ? (1.f / ssum) : 0.f;

    const float4 b0 = *(const float4*)(b + lane * 8);
    const float4 b1 = *(const float4*)(b + lane * 8 + 4);
    float o0 = fmaxf(acc[0] * inv + b0.x, 0.f);
    float o1 = fmaxf(acc[1] * inv + b0.y, 0.f);
    float o2 = fmaxf(acc[2] * inv + b0.z, 0.f);
    float o3 = fmaxf(acc[3] * inv + b0.w, 0.f);
    float o4 = fmaxf(acc[4] * inv + b1.x, 0.f);
    float o5 = fmaxf(acc[5] * inv + b1.y, 0.f);
    float o6 = fmaxf(acc[6] * inv + b1.z, 0.f);
    float o7 = fmaxf(acc[7] * inv + b1.w, 0.f);

    __half2 p0 = __floats2half2_rn(o0, o1);
    __half2 p1 = __floats2half2_rn(o2, o3);
    __half2 p2 = __floats2half2_rn(o4, o5);
    __half2 p3 = __floats2half2_rn(o6, o7);
    uint4 pk;
    pk.x = *(uint32_t*)&p0; pk.y = *(uint32_t*)&p1;
    pk.z = *(uint32_t*)&p2; pk.w = *(uint32_t*)&p3;
    ((uint4*)(out + n * HD))[lane] = pk;
}

// ---------------- CSR-structured dot scores (4-deep load batching) -------------
__global__ __launch_bounds__(256) void score_kernel(float* __restrict__ out) {
    const int w = (blockIdx.x * blockDim.x + threadIdx.x) >> 5;
    const int lane = threadIdx.x & 31;
    if (w >= 2 * NN) return;
    const bool pos = w < NN;
    const int n = pos ? w : w - NN;

    const int* offp = pos ? g_off : g_noff;
    const int off = offp[n];
    const int deg = offp[n + 1] - off;
    if (deg == 0) return;

    const uint4 vp = ((const uint4*)(g_hh + n * HD))[lane];
    const __half2* vh = (const __half2*)&vp;
    const float2 v0 = __half22float2(vh[0]), v1 = __half22float2(vh[1]);
    const float2 v2 = __half22float2(vh[2]), v3 = __half22float2(vh[3]);

    float* obase = out + (pos ? 0 : EE * HH);

    for (int base = 0; base < deg; base += 32) {
        const int myi = base + lane;
        int sv = 0, ev = 0;
        if (myi < deg) {
            if (pos) { sv = g_csr_src[off + myi]; ev = g_csr_eid[off + myi]; }
            else     { int2 t = g_ncsr[off + myi]; sv = t.x; ev = t.y; }
        }
        const int cnt = min(32, deg - base);
        int j = 0;
        for (; j + 4 <= cnt; j += 4) {
            int s[4], ei[4];
#pragma unroll
            for (int k = 0; k < 4; k++) {
                s[k]  = __shfl_sync(0xffffffffu, sv, j + k);
                ei[k] = __shfl_sync(0xffffffffu, ev, j + k);
            }
            uint4 up[4];
#pragma unroll
            for (int k = 0; k < 4; k++)
                up[k] = *(const uint4*)(g_hh + s[k] * HD + lane * 8);
#pragma unroll
            for (int k = 0; k < 4; k++) {
                const __half2* uh = (const __half2*)&up[k];
                const float2 u0 = __half22float2(uh[0]), u1 = __half22float2(uh[1]);
                const float2 u2 = __half22float2(uh[2]), u3 = __half22float2(uh[3]);
                float d = u0.x * v0.x + u0.y * v0.y + u1.x * v1.x + u1.y * v1.y +
                          u2.x * v2.x + u2.y * v2.y + u3.x * v3.x + u3.y * v3.y;
#pragma unroll
                for (int o = 4; o >= 1; o >>= 1) d += __shfl_down_sync(0xffffffffu, d, o, 8);
                if ((lane & 7) == 0) obase[ei[k] * HH + (lane >> 3)] = d;
            }
        }
        for (; j < cnt; j++) {
            const int s  = __shfl_sync(0xffffffffu, sv, j);
            const int ei = __shfl_sync(0xffffffffu, ev, j);
            const uint4 up = *(const uint4*)(g_hh + s * HD + lane * 8);
            const __half2* uh = (const __half2*)&up;
            const float2 u0 = __half22float2(uh[0]), u1 = __half22float2(uh[1]);
            const float2 u2 = __half22float2(uh[2]), u3 = __half22float2(uh[3]);
            float d = u0.x * v0.x + u0.y * v0.y + u1.x * v1.x + u1.y * v1.y +
                      u2.x * v2.x + u2.y * v2.y + u3.x * v3.x + u3.y * v3.y;
#pragma unroll
            for (int o = 4; o >= 1; o >>= 1) d += __shfl_down_sync(0xffffffffu, d, o, 8);
            if ((lane & 7) == 0) obase[ei * HH + (lane >> 3)] = d;
        }
    }
}

// ---------------- launch -------------------------------------------------------
extern "C" void kernel_launch(void* const* d_in, const int* in_sizes, int n_in,
                              void* d_out, int out_size) {
    const float* x    = (const float*)d_in[0];
    const int* src    = (const int*)d_in[1];
    const int* dst    = (const int*)d_in[2];
    const int* nsrc   = (const int*)d_in[3];
    const int* ndst   = (const int*)d_in[4];
    const float* W[3]  = {(const float*)d_in[5], (const float*)d_in[9],  (const float*)d_in[13]};
    const float* al[3] = {(const float*)d_in[6], (const float*)d_in[10], (const float*)d_in[14]};
    const float* ar[3] = {(const float*)d_in[7], (const float*)d_in[11], (const float*)d_in[15]};
    const float* bb[3] = {(const float*)d_in[8], (const float*)d_in[12], (const float*)d_in[16]};
    float* out = (float*)d_out;

    __half* actbuf = nullptr;
    cudaGetSymbolAddress((void**)&actbuf, g_act16);
    __half* featbuf = nullptr;
    cudaGetSymbolAddress((void**)&featbuf, g_feat16);
    __half* hhbuf = nullptr;
    cudaGetSymbolAddress((void**)&hhbuf, g_hh);
    __half* wbuf = nullptr;
    cudaGetSymbolAddress((void**)&wbuf, g_w16);
    int* cntbuf = nullptr;
    cudaGetSymbolAddress((void**)&cntbuf, g_cnt);
    int* ncntbuf = nullptr;
    cudaGetSymbolAddress((void**)&ncntbuf, g_ncnt);
    int* offbuf = nullptr;
    cudaGetSymbolAddress((void**)&offbuf, g_off);
    int* curbuf = nullptr;
    cudaGetSymbolAddress((void**)&curbuf, g_cur);
    int* noffbuf = nullptr;
    cudaGetSymbolAddress((void**)&noffbuf, g_noff);
    int* ncurbuf = nullptr;
    cudaGetSymbolAddress((void**)&ncurbuf, g_ncur);

    static cudaStream_t s_side = nullptr;
    static cudaEvent_t s_fork = nullptr, s_join1 = nullptr, s_join2 = nullptr;
    if (s_side == nullptr) {
        cudaStreamCreateWithFlags(&s_side, cudaStreamNonBlocking);
        cudaEventCreateWithFlags(&s_fork, cudaEventDisableTiming);
        cudaEventCreateWithFlags(&s_join1, cudaEventDisableTiming);
        cudaEventCreateWithFlags(&s_join2, cudaEventDisableTiming);
        const int scan_smem0 = NN * (int)sizeof(int);
        cudaFuncSetAttribute(csr_scan_kernel, cudaFuncAttributeMaxDynamicSharedMemorySize, scan_smem0);
    }

    const int scan_smem = NN * (int)sizeof(int);

    dim3 gemm_grid((NN + MT - 1) / MT, 2);   // (131, 2) = 262 CTAs: single wave
    const int cvt_blocks   = (NX4 + NW4 + 255) / 256;
    const int node_blocks  = (NN * 32 + 255) / 256;
    const int score_blocks = (2 * NN * 32 + 255) / 256;
    const int e_blocks     = (EE + 255) / 256;

    // ---- fork: CSR builds on side stream ----
    cudaEventRecord(s_fork, 0);
    cudaStreamWaitEvent(s_side, s_fork, 0);
    cudaMemsetAsync(cntbuf, 0, NN * sizeof(int), s_side);
    csr_hist_kernel<<<e_blocks, 256, 0, s_side>>>(dst, cntbuf);
    csr_scan_kernel<<<1, 1024, scan_smem, s_side>>>(cntbuf, offbuf, curbuf);
    csr_scatter_pos<<<e_blocks, 256, 0, s_side>>>(src, dst);
    cudaEventRecord(s_join1, s_side);
    cudaMemsetAsync(ncntbuf, 0, NN * sizeof(int), s_side);
    csr_hist_kernel<<<e_blocks, 256, 0, s_side>>>(ndst, ncntbuf);
    csr_scan_kernel<<<1, 1024, scan_smem, s_side>>>(ncntbuf, noffbuf, ncurbuf);
    csr_scatter_neg<<<e_blocks, 256, 0, s_side>>>(nsrc, ndst);
    cudaEventRecord(s_join2, s_side);

    // ---- main stream: converts + layer-1 GEMM (independent of CSR) ----
    cvt_all_kernel<<<cvt_blocks, 256>>>(x, W[0], W[1], W[2]);
    gemm_fused<<<gemm_grid, 256>>>(actbuf, wbuf, al[0], ar[0], featbuf);

    cudaStreamWaitEvent(0, s_join1, 0);
    fused_edge_kernel<<<node_blocks, 256>>>(bb[0], actbuf);
    for (int l = 1; l < 3; l++) {
        gemm_fused<<<gemm_grid, 256>>>(actbuf, wbuf + l * HD * HD, al[l], ar[l], featbuf);
        fused_edge_kernel<<<node_blocks, 256>>>(bb[l], (l == 2) ? hhbuf : actbuf);
    }
    cudaStreamWaitEvent(0, s_join2, 0);
    score_kernel<<<score_blocks, 256>>>(out);
}